// round 14
// baseline (speedup 1.0000x reference)
#include <cuda_runtime.h>
#include <cuda_bf16.h>
#include <math.h>
#include <stdint.h>
#include <stddef.h>

// ===========================================================================
// BlipAttention via mma.sync (HMMA bf16, sm_80-compatible PTX).
// fp32 accuracy via bf16 hi/lo split: D += Ahi*Bhi + Alo*Bhi + Ahi*Blo.
// Round 13: 3-stage cp.async pipeline, early commit (2 chunk-times of
// prefetch flight), single barrier per chunk. Rest = R8/R11 winner:
// 128-thread CTAs, 128x64 tile, BK=32, 3 CTAs/SM, fused epilogues.
// ===========================================================================

static __device__ __forceinline__ uint32_t smem_u32(const void* p) {
    uint32_t a;
    asm("{ .reg .u64 t; cvta.to.shared.u64 t, %1; cvt.u32.u64 %0, t; }"
        : "=r"(a) : "l"(p));
    return a;
}

#define CP_ASYNC(saddr, gaddr) \
    asm volatile("cp.async.cg.shared.global [%0], [%1], 16;" :: "r"(saddr), "l"(gaddr))
#define CP_COMMIT() asm volatile("cp.async.commit_group;" ::: "memory")
#define CP_WAIT(n)  asm volatile("cp.async.wait_group %0;" :: "n"(n) : "memory")

static __device__ __forceinline__ void ldm_x4(uint32_t* d, uint32_t addr) {
    asm volatile("ldmatrix.sync.aligned.m8n8.x4.shared.b16 {%0,%1,%2,%3}, [%4];"
                 : "=r"(d[0]), "=r"(d[1]), "=r"(d[2]), "=r"(d[3]) : "r"(addr));
}
static __device__ __forceinline__ void mma16816(float* c, const uint32_t* a,
                                                const uint32_t* b) {
    asm volatile(
        "mma.sync.aligned.m16n8k16.row.col.f32.bf16.bf16.f32 "
        "{%0,%1,%2,%3}, {%4,%5,%6,%7}, {%8,%9}, {%0,%1,%2,%3};"
        : "+f"(c[0]), "+f"(c[1]), "+f"(c[2]), "+f"(c[3])
        : "r"(a[0]), "r"(a[1]), "r"(a[2]), "r"(a[3]), "r"(b[0]), "r"(b[1]));
}
static __device__ __forceinline__ void split1(float x, __nv_bfloat16& h,
                                              __nv_bfloat16& l) {
    h = __float2bfloat16(x);
    l = __float2bfloat16(x - __bfloat162float(h));
}
// 64-byte-row swizzle: conflict-free for LDSM 8-row phases and store wavefronts.
static __device__ __forceinline__ int swz64(int r, int cb) {
    return r * 64 + (cb ^ ((r & 3) << 4) ^ ((r & 4) << 2));
}

// ---------------------------------------------------------------------------
// Pooled scratch (no allocation allowed). xhi/xlo reused by a5hi/a5lo.
// ---------------------------------------------------------------------------
static constexpr size_t O_XHI   = 0;            // 48 MB (-> a5hi)
static constexpr size_t O_XLO   = 50331648;     // 48 MB (-> a5lo)
static constexpr size_t O_W1HI  = 100663296;
static constexpr size_t O_W1LO  = 104202240;
static constexpr size_t O_W5HI  = 107741184;
static constexpr size_t O_W5LO  = 108920832;
static constexpr size_t O_QKHI  = 110100480;    // 96 MB (32768 x 1536 bf16)
static constexpr size_t O_QKLO  = 210763776;
static constexpr size_t O_VTHI  = 311427072;    // 48 MB (32 x 768 x 1024)
static constexpr size_t O_VTLO  = 361758720;
static constexpr size_t O_SC    = 412090368;    // 128 MB fp32 scores
static constexpr size_t O_PHI   = 546308096;    // 64 MB
static constexpr size_t O_PLO   = 613416960;    // 64 MB
static constexpr size_t POOL_SZ = 680525824;

__device__ __align__(1024) char g_pool[POOL_SZ];

// ---------------------------------------------------------------------------
// HMMA GEMM: 128x64 tile, BK=32 chunks, 3-stage cp.async pipeline, 4 warps
// (all stacked in m; warp tile 32x64). 3 CTAs/SM.
// Stage layout: Ahi(8K) | Alo(8K) | Bhi(4K) | Blo(4K) = 24KB. 3 stages = 72KB.
// EPI: 0 = fp32 (+bias opt) ; 1 = QKV split epilogue ; 2 = transposed split.
// ---------------------------------------------------------------------------
static constexpr int STAGE_BYTES = 24576;
static constexpr int NSTAGE      = 3;
static constexpr int SMEM_BYTES  = NSTAGE * STAGE_BYTES;   // 72 KB

template <int EPI, bool BIAS>
__global__ __launch_bounds__(128, 3)
void hgemm(const __nv_bfloat16* __restrict__ Ahi, const __nv_bfloat16* __restrict__ Alo,
           int lda, long sA,
           const __nv_bfloat16* __restrict__ Bhi, const __nv_bfloat16* __restrict__ Blo,
           int ldb, long sB,
           const float* __restrict__ bias,
           float* __restrict__ Cf,
           __nv_bfloat16* __restrict__ Chi, __nv_bfloat16* __restrict__ Clo,
           __nv_bfloat16* __restrict__ Vhi, __nv_bfloat16* __restrict__ Vlo,
           int ldc, long sC, int K, float qscale)
{
    extern __shared__ __align__(1024) char smem[];
    const int tid  = threadIdx.x;
    const int wid  = tid >> 5;
    const int lane = tid & 31;
    const long bz  = blockIdx.z;
    const int m0 = blockIdx.y * 128;
    const int n0 = blockIdx.x * 64;
    Ahi += bz * sA; Alo += bz * sA;
    Bhi += bz * sB; Blo += bz * sB;

    const uint32_t sbase = smem_u32(smem);
    const int NC = K >> 5;

    auto prefetch = [&](int ch, int s) {
        const uint32_t st = sbase + s * STAGE_BYTES;
        const int k0 = ch << 5;
        const char* gAh = (const char*)Ahi + ((long)m0 * lda + k0) * 2;
        const char* gAl = (const char*)Alo + ((long)m0 * lda + k0) * 2;
        const char* gBh = (const char*)Bhi + ((long)n0 * ldb + k0) * 2;
        const char* gBl = (const char*)Blo + ((long)n0 * ldb + k0) * 2;
        const long strA = (long)lda * 2;
        const long strB = (long)ldb * 2;
#pragma unroll
        for (int i = 0; i < 4; i++) {           // A: 128 rows x 64B
            const int idx = tid + (i << 7);
            const int r   = idx >> 2;
            const int cb  = (idx & 3) << 4;
            const int sw  = swz64(r, cb);
            CP_ASYNC(st + sw,        gAh + (long)r * strA + cb);
            CP_ASYNC(st + 8192 + sw, gAl + (long)r * strA + cb);
        }
#pragma unroll
        for (int i = 0; i < 2; i++) {           // B: 64 rows x 64B
            const int idx = tid + (i << 7);
            const int r   = idx >> 2;
            const int cb  = (idx & 3) << 4;
            const int sw  = swz64(r, cb);
            CP_ASYNC(st + 16384 + sw, gBh + (long)r * strB + cb);
            CP_ASYNC(st + 20480 + sw, gBl + (long)r * strB + cb);
        }
        CP_COMMIT();
    };

    const int mb = wid * 32;          // 4 warps stacked in m
    const int a_r  = (lane & 7) + ((lane >> 3) & 1) * 8;
    const int a_cb = (lane >> 4) * 16;
    const int b_r  = (lane & 7) + ((lane >> 4) & 1) * 8;
    const int b_cb = ((lane >> 3) & 1) * 16;

    float acc[2][8][4];
#pragma unroll
    for (int i = 0; i < 2; i++)
#pragma unroll
        for (int j = 0; j < 8; j++)
#pragma unroll
            for (int v = 0; v < 4; v++) acc[i][j][v] = 0.f;

    // Prologue: two chunks in flight.
    prefetch(0, 0);
    prefetch(1, 1);

    int stage = 0;
    for (int ch = 0; ch < NC; ch++) {
        // Stage `ch` was committed >= 2 iterations ago -> essentially free.
        if (ch + 1 < NC) { CP_WAIT(1); } else { CP_WAIT(0); }
        __syncthreads();
        // Early commit: buffer (ch+2)%3 was last read in iteration ch-1;
        // the barrier above guarantees all warps finished it.
        if (ch + 2 < NC) prefetch(ch + 2, (stage + 2 == NSTAGE) ? 0 :
                                          (stage + 2 == NSTAGE + 1) ? 1 : stage + 2);

        const uint32_t st   = sbase + stage * STAGE_BYTES;
        const uint32_t stAh = st;
        const uint32_t stAl = st + 8192;
        const uint32_t stBh = st + 16384;
        const uint32_t stBl = st + 20480;

#pragma unroll
        for (int ks = 0; ks < 2; ks++) {
            const int kcb = ks * 32;

            uint32_t ah[2][4], al[2][4];
#pragma unroll
            for (int i = 0; i < 2; i++) {
                const int r  = mb + i * 16 + a_r;
                const uint32_t off = swz64(r, kcb + a_cb);
                ldm_x4(ah[i], stAh + off);
                ldm_x4(al[i], stAl + off);
            }
            uint32_t bh[8][2], bl[8][2];
#pragma unroll
            for (int jj = 0; jj < 4; jj++) {
                const int r  = jj * 16 + b_r;
                const uint32_t off = swz64(r, kcb + b_cb);
                uint32_t t0[4], t1[4];
                ldm_x4(t0, stBh + off);
                ldm_x4(t1, stBl + off);
                bh[jj * 2][0] = t0[0]; bh[jj * 2][1] = t0[1];
                bh[jj * 2 + 1][0] = t0[2]; bh[jj * 2 + 1][1] = t0[3];
                bl[jj * 2][0] = t1[0]; bl[jj * 2][1] = t1[1];
                bl[jj * 2 + 1][0] = t1[2]; bl[jj * 2 + 1][1] = t1[3];
            }
#pragma unroll
            for (int i = 0; i < 2; i++) {
#pragma unroll
                for (int j = 0; j < 8; j++)
                    mma16816(acc[i][j], ah[i], bh[j]);
#pragma unroll
                for (int j = 0; j < 8; j++)
                    mma16816(acc[i][j], al[i], bh[j]);
#pragma unroll
                for (int j = 0; j < 8; j++)
                    mma16816(acc[i][j], ah[i], bl[j]);
            }
        }
        stage = (stage + 1 == NSTAGE) ? 0 : stage + 1;
    }

    // All warps must leave the mainloop before smem is reused by epilogues.
    __syncthreads();

    // ---------------- Epilogues ----------------
    const int g  = lane >> 2;
    const int cq = (lane & 3) * 2;

    if (EPI == 0) {
        float* C = Cf + bz * sC;
#pragma unroll
        for (int i = 0; i < 2; i++) {
            const int r0 = m0 + mb + i * 16 + g;
#pragma unroll
            for (int j = 0; j < 8; j++) {
                const int c = n0 + j * 8 + cq;
                float bx = 0.f, by = 0.f;
                if (BIAS) { bx = bias[c]; by = bias[c + 1]; }
                float2 v0 = make_float2(acc[i][j][0] + bx, acc[i][j][1] + by);
                float2 v1 = make_float2(acc[i][j][2] + bx, acc[i][j][3] + by);
                *(float2*)&C[(long)r0 * ldc + c]       = v0;
                *(float2*)&C[(long)(r0 + 8) * ldc + c] = v1;
            }
        }
        return;
    }

    if (EPI == 1 && n0 < 1536) {
        // Direct split store into QK buffer (ldc = 1536); scale Q columns.
        const float s_ = (n0 < 768) ? qscale : 1.f;
#pragma unroll
        for (int i = 0; i < 2; i++) {
            const int r0 = m0 + mb + i * 16 + g;
#pragma unroll
            for (int j = 0; j < 8; j++) {
                const int c = n0 + j * 8 + cq;
                const float bx = bias[c], by = bias[c + 1];
                float f0 = (acc[i][j][0] + bx) * s_;
                float f1 = (acc[i][j][1] + by) * s_;
                float f2 = (acc[i][j][2] + bx) * s_;
                float f3 = (acc[i][j][3] + by) * s_;
                __nv_bfloat16 h0, l0, h1, l1, h2, l2, h3, l3;
                split1(f0, h0, l0); split1(f1, h1, l1);
                split1(f2, h2, l2); split1(f3, h3, l3);
                __nv_bfloat162 hv, lv;
                hv.x = h0; hv.y = h1; lv.x = l0; lv.y = l1;
                *(__nv_bfloat162*)&Chi[(long)r0 * ldc + c] = hv;
                *(__nv_bfloat162*)&Clo[(long)r0 * ldc + c] = lv;
                hv.x = h2; hv.y = h3; lv.x = l2; lv.y = l3;
                *(__nv_bfloat162*)&Chi[(long)(r0 + 8) * ldc + c] = hv;
                *(__nv_bfloat162*)&Clo[(long)(r0 + 8) * ldc + c] = lv;
            }
        }
        return;
    }

    // Bounce epilogue (EPI==1 V-range, or EPI==2): transpose via SMEM.
    {
        float* sb = (float*)smem;   // [128][68]
#pragma unroll
        for (int i = 0; i < 2; i++) {
            const int rl = mb + i * 16 + g;
#pragma unroll
            for (int j = 0; j < 8; j++) {
                const int cl = j * 8 + cq;
                float bx = 0.f, by = 0.f;
                if (EPI == 1) { bx = bias[n0 + cl]; by = bias[n0 + cl + 1]; }
                sb[rl * 68 + cl]           = acc[i][j][0] + bx;
                sb[rl * 68 + cl + 1]       = acc[i][j][1] + by;
                sb[(rl + 8) * 68 + cl]     = acc[i][j][2] + bx;
                sb[(rl + 8) * 68 + cl + 1] = acc[i][j][3] + by;
            }
        }
        __syncthreads();

        const int c_l = tid >> 1;          // 0..63 output channel within tile
        const int mh  = (tid & 1) * 64;    // token half
        __nv_bfloat16 *H, *L;
        long base;
        if (EPI == 1) {
            const int b  = m0 >> 10;
            const int cg = n0 + c_l - 1536;
            const int tk = (m0 & 1023) + mh;
            base = (long)b * 786432 + (long)cg * 1024 + tk;
            H = Vhi; L = Vlo;
        } else {
            base = bz * sC + (long)(n0 + c_l) * ldc + m0 + mh;
            H = Chi; L = Clo;
        }
#pragma unroll
        for (int mm = 0; mm < 64; mm += 2) {
            const float f0 = sb[(mh + mm) * 68 + c_l];
            const float f1 = sb[(mh + mm + 1) * 68 + c_l];
            __nv_bfloat16 h0, l0, h1, l1;
            split1(f0, h0, l0); split1(f1, h1, l1);
            __nv_bfloat162 hv, lv;
            hv.x = h0; hv.y = h1; lv.x = l0; lv.y = l1;
            *(__nv_bfloat162*)&H[base + mm] = hv;
            *(__nv_bfloat162*)&L[base + mm] = lv;
        }
    }
}

// ---------------------------------------------------------------------------
// fp32 -> bf16 hi/lo split (row-major, batched)
// ---------------------------------------------------------------------------
__global__ __launch_bounds__(256) void split_kernel(
    const float* __restrict__ in, int lda, long sIn,
    __nv_bfloat16* __restrict__ hi, __nv_bfloat16* __restrict__ lo,
    int ldo, long sOut, unsigned C4, float scale)
{
    const long b = blockIdx.y;
    const unsigned idx = blockIdx.x * 256u + threadIdx.x;
    const unsigned row = idx / C4;
    const unsigned c4  = idx % C4;
    const float4 v = *(const float4*)(in + b * sIn + (long)row * lda + c4 * 4u);
    float x0 = v.x * scale, x1 = v.y * scale, x2 = v.z * scale, x3 = v.w * scale;
    __nv_bfloat16 h0, l0, h1, l1, h2, l2, h3, l3;
    split1(x0, h0, l0); split1(x1, h1, l1);
    split1(x2, h2, l2); split1(x3, h3, l3);
    const long o = b * sOut + (long)row * ldo + c4 * 4u;
    __nv_bfloat162* H = (__nv_bfloat162*)&hi[o];
    __nv_bfloat162* L = (__nv_bfloat162*)&lo[o];
    __nv_bfloat162 t;
    t.x = h0; t.y = h1; H[0] = t;
    t.x = h2; t.y = h3; H[1] = t;
    t.x = l0; t.y = l1; L[0] = t;
    t.x = l2; t.y = l3; L[1] = t;
}

// ---------------------------------------------------------------------------
// fp32 [R,C] -> transposed bf16 hi/lo [C,R] (weights prep)
// ---------------------------------------------------------------------------
__global__ __launch_bounds__(256) void tsplit_kernel(
    const float* __restrict__ in, int lda, long sIn,
    __nv_bfloat16* __restrict__ hi, __nv_bfloat16* __restrict__ lo,
    int ldo, long sOut)
{
    __shared__ float t[32][33];
    const long b = blockIdx.z;
    const int c0 = blockIdx.x * 32;
    const int r0 = blockIdx.y * 32;
    const int tx = threadIdx.x;
    const int ty = threadIdx.y;
    const float* ip = in + b * sIn;
#pragma unroll
    for (int j = 0; j < 4; j++)
        t[ty + j * 8][tx] = ip[(long)(r0 + ty + j * 8) * lda + c0 + tx];
    __syncthreads();
#pragma unroll
    for (int j = 0; j < 4; j++) {
        const float v = t[tx][ty + j * 8];
        __nv_bfloat16 h, l;
        split1(v, h, l);
        const long o = b * sOut + (long)(c0 + ty + j * 8) * ldo + r0 + tx;
        hi[o] = h;
        lo[o] = l;
    }
}

// ---------------------------------------------------------------------------
// Row softmax + fused hi/lo split: 32768 rows of 1024 fp32 -> P hi/lo bf16.
// ---------------------------------------------------------------------------
__global__ __launch_bounds__(256) void softmax_split(
    const float* __restrict__ S,
    __nv_bfloat16* __restrict__ phi, __nv_bfloat16* __restrict__ plo)
{
    const long row = blockIdx.x;
    const float4* p = reinterpret_cast<const float4*>(S + row * 1024);
    const int tid = threadIdx.x;

    float4 v = p[tid];
    float m = fmaxf(fmaxf(v.x, v.y), fmaxf(v.z, v.w));
#pragma unroll
    for (int o = 16; o > 0; o >>= 1)
        m = fmaxf(m, __shfl_xor_sync(0xffffffffu, m, o));

    __shared__ float redm[8];
    __shared__ float reds[8];
    if ((tid & 31) == 0) redm[tid >> 5] = m;
    __syncthreads();
    float rm = redm[0];
#pragma unroll
    for (int i = 1; i < 8; i++) rm = fmaxf(rm, redm[i]);

    v.x = __expf(v.x - rm);
    v.y = __expf(v.y - rm);
    v.z = __expf(v.z - rm);
    v.w = __expf(v.w - rm);

    float s = v.x + v.y + v.z + v.w;
#pragma unroll
    for (int o = 16; o > 0; o >>= 1)
        s += __shfl_xor_sync(0xffffffffu, s, o);
    if ((tid & 31) == 0) reds[tid >> 5] = s;
    __syncthreads();
    float rs = 0.f;
#pragma unroll
    for (int i = 0; i < 8; i++) rs += reds[i];

    const float inv = 1.f / rs;
    const float f0 = v.x * inv, f1 = v.y * inv, f2 = v.z * inv, f3 = v.w * inv;
    __nv_bfloat16 h0, l0, h1, l1, h2, l2, h3, l3;
    split1(f0, h0, l0); split1(f1, h1, l1);
    split1(f2, h2, l2); split1(f3, h3, l3);
    const long o = row * 1024 + tid * 4;
    __nv_bfloat162 t;
    t.x = h0; t.y = h1; *(__nv_bfloat162*)&phi[o]     = t;
    t.x = h2; t.y = h3; *(__nv_bfloat162*)&phi[o + 2] = t;
    t.x = l0; t.y = l1; *(__nv_bfloat162*)&plo[o]     = t;
    t.x = l2; t.y = l3; *(__nv_bfloat162*)&plo[o + 2] = t;
}

// ---------------------------------------------------------------------------
extern "C" void kernel_launch(void* const* d_in, const int* in_sizes, int n_in,
                              void* d_out, int out_size)
{
    const float* x      = (const float*)d_in[0];
    const float* qkv_w  = (const float*)d_in[1];
    const float* qkv_b  = (const float*)d_in[2];
    const float* proj_w = (const float*)d_in[3];
    const float* proj_b = (const float*)d_in[4];
    float* out = (float*)d_out;

    char* pool;
    cudaGetSymbolAddress((void**)&pool, g_pool);

    __nv_bfloat16* xhi  = (__nv_bfloat16*)(pool + O_XHI);
    __nv_bfloat16* xlo  = (__nv_bfloat16*)(pool + O_XLO);
    __nv_bfloat16* w1hi = (__nv_bfloat16*)(pool + O_W1HI);
    __nv_bfloat16* w1lo = (__nv_bfloat16*)(pool + O_W1LO);
    __nv_bfloat16* w5hi = (__nv_bfloat16*)(pool + O_W5HI);
    __nv_bfloat16* w5lo = (__nv_bfloat16*)(pool + O_W5LO);
    __nv_bfloat16* qkhi = (__nv_bfloat16*)(pool + O_QKHI);
    __nv_bfloat16* qklo = (__nv_bfloat16*)(pool + O_QKLO);
    __nv_bfloat16* vthi = (__nv_bfloat16*)(pool + O_VTHI);
    __nv_bfloat16* vtlo = (__nv_bfloat16*)(pool + O_VTLO);
    float*         sc   = (float*)(pool + O_SC);
    __nv_bfloat16* phi  = (__nv_bfloat16*)(pool + O_PHI);
    __nv_bfloat16* plo  = (__nv_bfloat16*)(pool + O_PLO);
    __nv_bfloat16* a5hi = (__nv_bfloat16*)(pool + O_XHI);  // reuse (x dead)
    __nv_bfloat16* a5lo = (__nv_bfloat16*)(pool + O_XLO);

    cudaFuncSetAttribute(hgemm<0, true>,  cudaFuncAttributeMaxDynamicSharedMemorySize, SMEM_BYTES);
    cudaFuncSetAttribute(hgemm<0, false>, cudaFuncAttributeMaxDynamicSharedMemorySize, SMEM_BYTES);
    cudaFuncSetAttribute(hgemm<1, true>,  cudaFuncAttributeMaxDynamicSharedMemorySize, SMEM_BYTES);
    cudaFuncSetAttribute(hgemm<2, false>, cudaFuncAttributeMaxDynamicSharedMemorySize, SMEM_BYTES);

    const float scale = 1.0f / sqrtf(768.0f);

    // Operand prep
    split_kernel<<<(32768u * 192u) / 256u, 256>>>(x, 768, 0, xhi, xlo, 768, 0, 192u, 1.f);
    tsplit_kernel<<<dim3(2304 / 32, 768 / 32, 1), dim3(32, 8)>>>(
        qkv_w, 2304, 0, w1hi, w1lo, 768, 0);
    tsplit_kernel<<<dim3(768 / 32, 768 / 32, 1), dim3(32, 8)>>>(
        proj_w, 768, 0, w5hi, w5lo, 768, 0);

    // 1) qkv GEMM, fused epilogue: QK(hi/lo, Q pre-scaled) + V^T(hi/lo)
    hgemm<1, true><<<dim3(36, 256, 1), 128, SMEM_BYTES>>>(
        xhi, xlo, 768, 0, w1hi, w1lo, 768, 0, qkv_b,
        nullptr, qkhi, qklo, vthi, vtlo, 1536, 0, 768, scale);

    // 2) S = (Q*s) @ K^T : per-batch 1024x1024x768, fp32 out
    hgemm<0, false><<<dim3(16, 8, 32), 128, SMEM_BYTES>>>(
        qkhi, qklo, 1536, 1572864L, qkhi + 768, qklo + 768, 1536, 1572864L,
        nullptr, sc, nullptr, nullptr, nullptr, nullptr, 1024, 1048576L, 768, 1.f);

    // 3) softmax + split -> P hi/lo
    softmax_split<<<32 * 1024, 256>>>(sc, phi, plo);

    // 4) O = P @ V, fused transposed split epilogue -> A5 hi/lo
    hgemm<2, false><<<dim3(12, 8, 32), 128, SMEM_BYTES>>>(
        phi, plo, 1024, 1048576L, vthi, vtlo, 1024, 786432L, nullptr,
        nullptr, a5hi, a5lo, nullptr, nullptr, 1024, 786432L, 1024, 1.f);

    // 5) out = A5 @ proj_w + proj_b
    hgemm<0, true><<<dim3(12, 256, 1), 128, SMEM_BYTES>>>(
        a5hi, a5lo, 768, 0, w5hi, w5lo, 768, 0, proj_b,
        out, nullptr, nullptr, nullptr, nullptr, 768, 0, 768, 1.f);
}

// round 17
// speedup vs baseline: 1.4682x; 1.4682x over previous
#include <cuda_runtime.h>
#include <cuda_fp16.h>
#include <math.h>
#include <stdint.h>
#include <stddef.h>

// ===========================================================================
// BlipAttention via mma.sync (HMMA fp16, sm_80-compatible PTX).
// Round 15: fp16 (e5m10) asymmetric 2-pass split — D = Ahi*Bhi + Alo*Bhi,
// B only rounded (dropped A*Blo term ~2.8e-4/GEMM, calibrated model).
// Cuts GEMM FLOPs to 2/3 of the bf16 3-pass scheme. Mainloop = R12 winner
// (2-stage cp.async, 128-thr CTAs, 128x64 tile, BK=32, 3 CTAs/SM).
// The 1/sqrt(C) scale moves into the softmax so Q-lo stays fp16-normal.
// ===========================================================================

static __device__ __forceinline__ uint32_t smem_u32(const void* p) {
    uint32_t a;
    asm("{ .reg .u64 t; cvta.to.shared.u64 t, %1; cvt.u32.u64 %0, t; }"
        : "=r"(a) : "l"(p));
    return a;
}

#define CP_ASYNC(saddr, gaddr) \
    asm volatile("cp.async.cg.shared.global [%0], [%1], 16;" :: "r"(saddr), "l"(gaddr))
#define CP_COMMIT() asm volatile("cp.async.commit_group;" ::: "memory")
#define CP_WAIT(n)  asm volatile("cp.async.wait_group %0;" :: "n"(n) : "memory")

static __device__ __forceinline__ void ldm_x4(uint32_t* d, uint32_t addr) {
    asm volatile("ldmatrix.sync.aligned.m8n8.x4.shared.b16 {%0,%1,%2,%3}, [%4];"
                 : "=r"(d[0]), "=r"(d[1]), "=r"(d[2]), "=r"(d[3]) : "r"(addr));
}
static __device__ __forceinline__ void mma16816(float* c, const uint32_t* a,
                                                const uint32_t* b) {
    asm volatile(
        "mma.sync.aligned.m16n8k16.row.col.f32.f16.f16.f32 "
        "{%0,%1,%2,%3}, {%4,%5,%6,%7}, {%8,%9}, {%0,%1,%2,%3};"
        : "+f"(c[0]), "+f"(c[1]), "+f"(c[2]), "+f"(c[3])
        : "r"(a[0]), "r"(a[1]), "r"(a[2]), "r"(a[3]), "r"(b[0]), "r"(b[1]));
}
static __device__ __forceinline__ void split1(float x, __half& h, __half& l) {
    h = __float2half(x);
    l = __float2half(x - __half2float(h));
}
// 64-byte-row swizzle: conflict-free for LDSM 8-row phases and store wavefronts.
static __device__ __forceinline__ int swz64(int r, int cb) {
    return r * 64 + (cb ^ ((r & 3) << 4) ^ ((r & 4) << 2));
}

// ---------------------------------------------------------------------------
// Pooled scratch (no allocation allowed). xhi/xlo reused by a5hi/a5lo.
// ---------------------------------------------------------------------------
static constexpr size_t O_XHI   = 0;            // 48 MB (-> a5hi)
static constexpr size_t O_XLO   = 50331648;     // 48 MB (-> a5lo)
static constexpr size_t O_W1HI  = 100663296;
static constexpr size_t O_W1LO  = 104202240;
static constexpr size_t O_W5HI  = 107741184;
static constexpr size_t O_W5LO  = 108920832;
static constexpr size_t O_QKHI  = 110100480;    // 96 MB (32768 x 1536 fp16)
static constexpr size_t O_QKLO  = 210763776;
static constexpr size_t O_VTHI  = 311427072;    // 48 MB (32 x 768 x 1024)
static constexpr size_t O_VTLO  = 361758720;    // (unused in 2-pass scheme)
static constexpr size_t O_SC    = 412090368;    // 128 MB fp32 scores
static constexpr size_t O_PHI   = 546308096;    // 64 MB
static constexpr size_t O_PLO   = 613416960;    // 64 MB
static constexpr size_t POOL_SZ = 680525824;

__device__ __align__(1024) char g_pool[POOL_SZ];

// ---------------------------------------------------------------------------
// HMMA GEMM: 128x64 tile, BK=32 chunks, 2-stage cp.async, 4 warps (stacked
// in m; warp tile 32x64). 3 CTAs/SM.
// Stage layout: Ahi(8K) | Alo(8K) | Bhi(4K) = 20KB. 2 stages = 40KB.
// 2-pass mainloop: acc += Ahi*Bhi ; acc += Alo*Bhi.
// EPI: 0 = fp32 (+bias opt) ; 1 = QKV split epilogue ; 2 = transposed split.
// ---------------------------------------------------------------------------
static constexpr int STAGE_BYTES = 20480;
static constexpr int SMEM_BYTES  = 2 * STAGE_BYTES;   // 40 KB

template <int EPI, bool BIAS>
__global__ __launch_bounds__(128, 3)
void hgemm(const __half* __restrict__ Ahi, const __half* __restrict__ Alo,
           int lda, long sA,
           const __half* __restrict__ Bhi, int ldb, long sB,
           const float* __restrict__ bias,
           float* __restrict__ Cf,
           __half* __restrict__ Chi, __half* __restrict__ Clo,
           __half* __restrict__ Vhi,
           int ldc, long sC, int K)
{
    extern __shared__ __align__(1024) char smem[];
    const int tid  = threadIdx.x;
    const int wid  = tid >> 5;
    const int lane = tid & 31;
    const long bz  = blockIdx.z;
    const int m0 = blockIdx.y * 128;
    const int n0 = blockIdx.x * 64;
    Ahi += bz * sA; Alo += bz * sA;
    Bhi += bz * sB;

    const uint32_t sbase = smem_u32(smem);
    const int NC = K >> 5;

    auto prefetch = [&](int ch, int s) {
        const uint32_t st = sbase + s * STAGE_BYTES;
        const int k0 = ch << 5;
        const char* gAh = (const char*)Ahi + ((long)m0 * lda + k0) * 2;
        const char* gAl = (const char*)Alo + ((long)m0 * lda + k0) * 2;
        const char* gBh = (const char*)Bhi + ((long)n0 * ldb + k0) * 2;
        const long strA = (long)lda * 2;
        const long strB = (long)ldb * 2;
#pragma unroll
        for (int i = 0; i < 4; i++) {           // A: 128 rows x 64B
            const int idx = tid + (i << 7);
            const int r   = idx >> 2;
            const int cb  = (idx & 3) << 4;
            const int sw  = swz64(r, cb);
            CP_ASYNC(st + sw,        gAh + (long)r * strA + cb);
            CP_ASYNC(st + 8192 + sw, gAl + (long)r * strA + cb);
        }
#pragma unroll
        for (int i = 0; i < 2; i++) {           // B: 64 rows x 64B
            const int idx = tid + (i << 7);
            const int r   = idx >> 2;
            const int cb  = (idx & 3) << 4;
            const int sw  = swz64(r, cb);
            CP_ASYNC(st + 16384 + sw, gBh + (long)r * strB + cb);
        }
        CP_COMMIT();
    };

    const int mb = wid * 32;          // 4 warps stacked in m
    const int a_r  = (lane & 7) + ((lane >> 3) & 1) * 8;
    const int a_cb = (lane >> 4) * 16;
    const int b_r  = (lane & 7) + ((lane >> 4) & 1) * 8;
    const int b_cb = ((lane >> 3) & 1) * 16;

    float acc[2][8][4];
#pragma unroll
    for (int i = 0; i < 2; i++)
#pragma unroll
        for (int j = 0; j < 8; j++)
#pragma unroll
            for (int v = 0; v < 4; v++) acc[i][j][v] = 0.f;

    prefetch(0, 0);

    for (int ch = 0; ch < NC; ch++) {
        if (ch + 1 < NC) { prefetch(ch + 1, (ch + 1) & 1); CP_WAIT(1); }
        else             { CP_WAIT(0); }
        __syncthreads();

        const uint32_t st   = sbase + (ch & 1) * STAGE_BYTES;
        const uint32_t stAh = st;
        const uint32_t stAl = st + 8192;
        const uint32_t stBh = st + 16384;

#pragma unroll
        for (int ks = 0; ks < 2; ks++) {
            const int kcb = ks * 32;

            uint32_t ah[2][4], al[2][4];
#pragma unroll
            for (int i = 0; i < 2; i++) {
                const int r  = mb + i * 16 + a_r;
                const uint32_t off = swz64(r, kcb + a_cb);
                ldm_x4(ah[i], stAh + off);
                ldm_x4(al[i], stAl + off);
            }
            uint32_t bh[8][2];
#pragma unroll
            for (int jj = 0; jj < 4; jj++) {
                const int r  = jj * 16 + b_r;
                const uint32_t off = swz64(r, kcb + b_cb);
                uint32_t t0[4];
                ldm_x4(t0, stBh + off);
                bh[jj * 2][0] = t0[0]; bh[jj * 2][1] = t0[1];
                bh[jj * 2 + 1][0] = t0[2]; bh[jj * 2 + 1][1] = t0[3];
            }
#pragma unroll
            for (int i = 0; i < 2; i++) {
#pragma unroll
                for (int j = 0; j < 8; j++)
                    mma16816(acc[i][j], ah[i], bh[j]);
#pragma unroll
                for (int j = 0; j < 8; j++)
                    mma16816(acc[i][j], al[i], bh[j]);
            }
        }
        __syncthreads();
    }

    // ---------------- Epilogues ----------------
    const int g  = lane >> 2;
    const int cq = (lane & 3) * 2;

    if (EPI == 0) {
        float* C = Cf + bz * sC;
#pragma unroll
        for (int i = 0; i < 2; i++) {
            const int r0 = m0 + mb + i * 16 + g;
#pragma unroll
            for (int j = 0; j < 8; j++) {
                const int c = n0 + j * 8 + cq;
                float bx = 0.f, by = 0.f;
                if (BIAS) { bx = bias[c]; by = bias[c + 1]; }
                float2 v0 = make_float2(acc[i][j][0] + bx, acc[i][j][1] + by);
                float2 v1 = make_float2(acc[i][j][2] + bx, acc[i][j][3] + by);
                *(float2*)&C[(long)r0 * ldc + c]       = v0;
                *(float2*)&C[(long)(r0 + 8) * ldc + c] = v1;
            }
        }
        return;
    }

    if (EPI == 1 && n0 < 1536) {
        // Direct split store into QK buffer (ldc = 1536). No pre-scale:
        // the 1/sqrt(C) moves into the softmax.
#pragma unroll
        for (int i = 0; i < 2; i++) {
            const int r0 = m0 + mb + i * 16 + g;
#pragma unroll
            for (int j = 0; j < 8; j++) {
                const int c = n0 + j * 8 + cq;
                const float bx = bias[c], by = bias[c + 1];
                float f0 = acc[i][j][0] + bx;
                float f1 = acc[i][j][1] + by;
                float f2 = acc[i][j][2] + bx;
                float f3 = acc[i][j][3] + by;
                __half h0, l0, h1, l1, h2, l2, h3, l3;
                split1(f0, h0, l0); split1(f1, h1, l1);
                split1(f2, h2, l2); split1(f3, h3, l3);
                __half2 hv, lv;
                hv.x = h0; hv.y = h1; lv.x = l0; lv.y = l1;
                *(__half2*)&Chi[(long)r0 * ldc + c] = hv;
                *(__half2*)&Clo[(long)r0 * ldc + c] = lv;
                hv.x = h2; hv.y = h3; lv.x = l2; lv.y = l3;
                *(__half2*)&Chi[(long)(r0 + 8) * ldc + c] = hv;
                *(__half2*)&Clo[(long)(r0 + 8) * ldc + c] = lv;
            }
        }
        return;
    }

    // Bounce epilogue (EPI==1 V-range, or EPI==2): transpose via SMEM.
    {
        float* sb = (float*)smem;   // [128][68]
#pragma unroll
        for (int i = 0; i < 2; i++) {
            const int rl = mb + i * 16 + g;
#pragma unroll
            for (int j = 0; j < 8; j++) {
                const int cl = j * 8 + cq;
                float bx = 0.f, by = 0.f;
                if (EPI == 1) { bx = bias[n0 + cl]; by = bias[n0 + cl + 1]; }
                sb[rl * 68 + cl]           = acc[i][j][0] + bx;
                sb[rl * 68 + cl + 1]       = acc[i][j][1] + by;
                sb[(rl + 8) * 68 + cl]     = acc[i][j][2] + bx;
                sb[(rl + 8) * 68 + cl + 1] = acc[i][j][3] + by;
            }
        }
        __syncthreads();

        const int c_l = tid >> 1;          // 0..63 output channel within tile
        const int mh  = (tid & 1) * 64;    // token half
        if (EPI == 1) {
            // V^T: B operand of GEMM4 -> hi only.
            const int b  = m0 >> 10;
            const int cg = n0 + c_l - 1536;
            const int tk = (m0 & 1023) + mh;
            const long base = (long)b * 786432 + (long)cg * 1024 + tk;
#pragma unroll
            for (int mm = 0; mm < 64; mm += 2) {
                const float f0 = sb[(mh + mm) * 68 + c_l];
                const float f1 = sb[(mh + mm + 1) * 68 + c_l];
                __half2 hv;
                hv.x = __float2half(f0); hv.y = __float2half(f1);
                *(__half2*)&Vhi[base + mm] = hv;
            }
        } else {
            // A5^T: A operand of GEMM5 -> hi + lo.
            const long base = bz * sC + (long)(n0 + c_l) * ldc + m0 + mh;
#pragma unroll
            for (int mm = 0; mm < 64; mm += 2) {
                const float f0 = sb[(mh + mm) * 68 + c_l];
                const float f1 = sb[(mh + mm + 1) * 68 + c_l];
                __half h0, l0, h1, l1;
                split1(f0, h0, l0); split1(f1, h1, l1);
                __half2 hv, lv;
                hv.x = h0; hv.y = h1; lv.x = l0; lv.y = l1;
                *(__half2*)&Chi[base + mm] = hv;
                *(__half2*)&Clo[base + mm] = lv;
            }
        }
    }
}

// ---------------------------------------------------------------------------
// fp32 -> fp16 hi/lo split (row-major, batched)
// ---------------------------------------------------------------------------
__global__ __launch_bounds__(256) void split_kernel(
    const float* __restrict__ in, int lda, long sIn,
    __half* __restrict__ hi, __half* __restrict__ lo,
    int ldo, long sOut, unsigned C4, float scale)
{
    const long b = blockIdx.y;
    const unsigned idx = blockIdx.x * 256u + threadIdx.x;
    const unsigned row = idx / C4;
    const unsigned c4  = idx % C4;
    const float4 v = *(const float4*)(in + b * sIn + (long)row * lda + c4 * 4u);
    float x0 = v.x * scale, x1 = v.y * scale, x2 = v.z * scale, x3 = v.w * scale;
    __half h0, l0, h1, l1, h2, l2, h3, l3;
    split1(x0, h0, l0); split1(x1, h1, l1);
    split1(x2, h2, l2); split1(x3, h3, l3);
    const long o = b * sOut + (long)row * ldo + c4 * 4u;
    __half2* H = (__half2*)&hi[o];
    __half2* L = (__half2*)&lo[o];
    __half2 t;
    t.x = h0; t.y = h1; H[0] = t;
    t.x = h2; t.y = h3; H[1] = t;
    t.x = l0; t.y = l1; L[0] = t;
    t.x = l2; t.y = l3; L[1] = t;
}

// ---------------------------------------------------------------------------
// fp32 [R,C] -> transposed fp16 hi [C,R] (weights prep; B operand -> hi only)
// ---------------------------------------------------------------------------
__global__ __launch_bounds__(256) void tsplit_kernel(
    const float* __restrict__ in, int lda, long sIn,
    __half* __restrict__ hi, int ldo, long sOut)
{
    __shared__ float t[32][33];
    const long b = blockIdx.z;
    const int c0 = blockIdx.x * 32;
    const int r0 = blockIdx.y * 32;
    const int tx = threadIdx.x;
    const int ty = threadIdx.y;
    const float* ip = in + b * sIn;
#pragma unroll
    for (int j = 0; j < 4; j++)
        t[ty + j * 8][tx] = ip[(long)(r0 + ty + j * 8) * lda + c0 + tx];
    __syncthreads();
#pragma unroll
    for (int j = 0; j < 4; j++) {
        const float v = t[tx][ty + j * 8];
        const long o = b * sOut + (long)(c0 + ty + j * 8) * ldo + r0 + tx;
        hi[o] = __float2half(v);
    }
}

// ---------------------------------------------------------------------------
// Row softmax (with fused 1/sqrt(C) pre-scale) + fp16 hi/lo split.
// 32768 rows of 1024 fp32 -> P hi/lo fp16.
// ---------------------------------------------------------------------------
__global__ __launch_bounds__(256) void softmax_split(
    const float* __restrict__ S,
    __half* __restrict__ phi, __half* __restrict__ plo, float scale)
{
    const long row = blockIdx.x;
    const float4* p = reinterpret_cast<const float4*>(S + row * 1024);
    const int tid = threadIdx.x;

    float4 v = p[tid];
    v.x *= scale; v.y *= scale; v.z *= scale; v.w *= scale;
    float m = fmaxf(fmaxf(v.x, v.y), fmaxf(v.z, v.w));
#pragma unroll
    for (int o = 16; o > 0; o >>= 1)
        m = fmaxf(m, __shfl_xor_sync(0xffffffffu, m, o));

    __shared__ float redm[8];
    __shared__ float reds[8];
    if ((tid & 31) == 0) redm[tid >> 5] = m;
    __syncthreads();
    float rm = redm[0];
#pragma unroll
    for (int i = 1; i < 8; i++) rm = fmaxf(rm, redm[i]);

    v.x = __expf(v.x - rm);
    v.y = __expf(v.y - rm);
    v.z = __expf(v.z - rm);
    v.w = __expf(v.w - rm);

    float s = v.x + v.y + v.z + v.w;
#pragma unroll
    for (int o = 16; o > 0; o >>= 1)
        s += __shfl_xor_sync(0xffffffffu, s, o);
    if ((tid & 31) == 0) reds[tid >> 5] = s;
    __syncthreads();
    float rs = 0.f;
#pragma unroll
    for (int i = 0; i < 8; i++) rs += reds[i];

    const float inv = 1.f / rs;
    const float f0 = v.x * inv, f1 = v.y * inv, f2 = v.z * inv, f3 = v.w * inv;
    __half h0, l0, h1, l1, h2, l2, h3, l3;
    split1(f0, h0, l0); split1(f1, h1, l1);
    split1(f2, h2, l2); split1(f3, h3, l3);
    const long o = row * 1024 + tid * 4;
    __half2 t;
    t.x = h0; t.y = h1; *(__half2*)&phi[o]     = t;
    t.x = h2; t.y = h3; *(__half2*)&phi[o + 2] = t;
    t.x = l0; t.y = l1; *(__half2*)&plo[o]     = t;
    t.x = l2; t.y = l3; *(__half2*)&plo[o + 2] = t;
}

// ---------------------------------------------------------------------------
extern "C" void kernel_launch(void* const* d_in, const int* in_sizes, int n_in,
                              void* d_out, int out_size)
{
    const float* x      = (const float*)d_in[0];
    const float* qkv_w  = (const float*)d_in[1];
    const float* qkv_b  = (const float*)d_in[2];
    const float* proj_w = (const float*)d_in[3];
    const float* proj_b = (const float*)d_in[4];
    float* out = (float*)d_out;

    char* pool;
    cudaGetSymbolAddress((void**)&pool, g_pool);

    __half* xhi  = (__half*)(pool + O_XHI);
    __half* xlo  = (__half*)(pool + O_XLO);
    __half* w1hi = (__half*)(pool + O_W1HI);
    __half* w5hi = (__half*)(pool + O_W5HI);
    __half* qkhi = (__half*)(pool + O_QKHI);
    __half* qklo = (__half*)(pool + O_QKLO);
    __half* vthi = (__half*)(pool + O_VTHI);
    float*  sc   = (float*)(pool + O_SC);
    __half* phi  = (__half*)(pool + O_PHI);
    __half* plo  = (__half*)(pool + O_PLO);
    __half* a5hi = (__half*)(pool + O_XHI);   // reuse (x dead)
    __half* a5lo = (__half*)(pool + O_XLO);

    cudaFuncSetAttribute(hgemm<0, true>,  cudaFuncAttributeMaxDynamicSharedMemorySize, SMEM_BYTES);
    cudaFuncSetAttribute(hgemm<0, false>, cudaFuncAttributeMaxDynamicSharedMemorySize, SMEM_BYTES);
    cudaFuncSetAttribute(hgemm<1, true>,  cudaFuncAttributeMaxDynamicSharedMemorySize, SMEM_BYTES);
    cudaFuncSetAttribute(hgemm<2, false>, cudaFuncAttributeMaxDynamicSharedMemorySize, SMEM_BYTES);

    const float scale = 1.0f / sqrtf(768.0f);

    // Operand prep (A operands: hi+lo ; B operands: hi only)
    split_kernel<<<(32768u * 192u) / 256u, 256>>>(x, 768, 0, xhi, xlo, 768, 0, 192u, 1.f);
    tsplit_kernel<<<dim3(2304 / 32, 768 / 32, 1), dim3(32, 8)>>>(
        qkv_w, 2304, 0, w1hi, 768, 0);
    tsplit_kernel<<<dim3(768 / 32, 768 / 32, 1), dim3(32, 8)>>>(
        proj_w, 768, 0, w5hi, 768, 0);

    // 1) qkv GEMM, fused epilogue: QK(hi/lo) + V^T(hi)
    hgemm<1, true><<<dim3(36, 256, 1), 128, SMEM_BYTES>>>(
        xhi, xlo, 768, 0, w1hi, 768, 0, qkv_b,
        nullptr, qkhi, qklo, vthi, 1536, 0, 768);

    // 2) S = Q @ K^T : per-batch 1024x1024x768, fp32 out (scale in softmax)
    hgemm<0, false><<<dim3(16, 8, 32), 128, SMEM_BYTES>>>(
        qkhi, qklo, 1536, 1572864L, qkhi + 768, 1536, 1572864L,
        nullptr, sc, nullptr, nullptr, nullptr, 1024, 1048576L, 768);

    // 3) softmax (pre-scaled) + split -> P hi/lo
    softmax_split<<<32 * 1024, 256>>>(sc, phi, plo, scale);

    // 4) O = P @ V, fused transposed split epilogue -> A5 hi/lo
    hgemm<2, false><<<dim3(12, 8, 32), 128, SMEM_BYTES>>>(
        phi, plo, 1024, 1048576L, vthi, 1024, 786432L, nullptr,
        nullptr, a5hi, a5lo, nullptr, 1024, 786432L, 1024);

    // 5) out = A5 @ proj_w + proj_b
    hgemm<0, true><<<dim3(12, 256, 1), 128, SMEM_BYTES>>>(
        a5hi, a5lo, 768, 0, w5hi, 768, 0, proj_b,
        out, nullptr, nullptr, nullptr, 768, 0, 768);
}